// round 6
// baseline (speedup 1.0000x reference)
#include <cuda_runtime.h>
#include <cuda_bf16.h>

// Embedding gather: out[i, :] = table[ids[i], :]
// ids: int32 [819200], table: f32 [1e6, 32] (~128 MB; unique working set ~72 MB fits L2),
// out: f32 [819200, 32]
//
//  - table loads use an L2::evict_last cache policy (keep touched rows L2-resident)
//  - output stores use .cs streaming (write-once; don't evict the table)
//  - 8 independent row-gathers per thread for memory-level parallelism

#define NSEG 8

__device__ __forceinline__ float4 ldg_table(const float4* p, unsigned long long pol) {
    float4 v;
    asm volatile("ld.global.nc.L2::cache_hint.v4.f32 {%0,%1,%2,%3}, [%4], %5;"
                 : "=f"(v.x), "=f"(v.y), "=f"(v.z), "=f"(v.w)
                 : "l"(p), "l"(pol));
    return v;
}

__device__ __forceinline__ void stg_stream(float4* p, float4 v) {
    asm volatile("st.global.cs.v4.f32 [%0], {%1,%2,%3,%4};"
                 :: "l"(p), "f"(v.x), "f"(v.y), "f"(v.z), "f"(v.w)
                 : "memory");
}

__global__ void __launch_bounds__(256)
embedding_gather_kernel(const int* __restrict__ ids,
                        const float4* __restrict__ table4,
                        float4* __restrict__ out4,
                        int seg) {
    int i = blockIdx.x * blockDim.x + threadIdx.x;
    if (i >= seg) return;

    unsigned long long pol;
    asm volatile("createpolicy.fractional.L2::evict_last.b64 %0, 1.0;" : "=l"(pol));

    int idx[NSEG];
    int id[NSEG];
#pragma unroll
    for (int s = 0; s < NSEG; s++) {
        idx[s] = i + s * seg;
        id[s]  = __ldg(&ids[idx[s] >> 3]);
    }

    float4 v[NSEG];
#pragma unroll
    for (int s = 0; s < NSEG; s++)
        v[s] = ldg_table(&table4[(size_t)(unsigned)id[s] * 8 + (idx[s] & 7)], pol);

#pragma unroll
    for (int s = 0; s < NSEG; s++)
        stg_stream(&out4[idx[s]], v[s]);
}

extern "C" void kernel_launch(void* const* d_in, const int* in_sizes, int n_in,
                              void* d_out, int out_size) {
    // Resolve inputs by element count (table: 32,000,000 f32; ids: 819,200).
    const int*    ids;
    const float4* table;
    int n_rows;
    if (in_sizes[0] > in_sizes[1]) {
        table = (const float4*)d_in[0];
        ids   = (const int*)d_in[1];
        n_rows = in_sizes[1];
    } else {
        ids   = (const int*)d_in[0];
        table = (const float4*)d_in[1];
        n_rows = in_sizes[0];
    }

    float4* out = (float4*)d_out;
    int n4 = n_rows * 8;          // total float4 elements (divisible by NSEG)
    int seg = n4 / NSEG;
    int threads = 256;
    int blocks = (seg + threads - 1) / threads;
    embedding_gather_kernel<<<blocks, threads>>>(ids, table, out, seg);
}